// round 5
// baseline (speedup 1.0000x reference)
#include <cuda_runtime.h>
#include <cstdint>

// Problem constants
#define Hc    128
#define H1c   129
#define FUSE  (H1c*H1c*H1c)     // 2,146,689
#define Bq    64                // batch
#define N1    64                // H/2
#define N2    32                // H/4
#define TK    32                // k-tile
#define NCTA  304               // 2 per SM on 152 SMs
#define NTHR  256

// Scratch (no cudaMalloc allowed)
__device__ float g_partial[NCTA * Bq * N1];   // ~4.9 MB
__device__ float g_Y1[Bq * N1];

// ---------- packed f32x2 helpers ----------
__device__ __forceinline__ unsigned long long pack2(float lo, float hi) {
    unsigned long long r;
    asm("mov.b64 %0, {%1, %2};" : "=l"(r)
        : "r"(__float_as_uint(lo)), "r"(__float_as_uint(hi)));
    return r;
}
__device__ __forceinline__ void unpack2(unsigned long long x, float &lo, float &hi) {
    unsigned a, b;
    asm("mov.b64 {%0, %1}, %2;" : "=r"(a), "=r"(b) : "l"(x));
    lo = __uint_as_float(a); hi = __uint_as_float(b);
}
__device__ __forceinline__ void ffma2(unsigned long long &acc,
                                      unsigned long long a, unsigned long long b) {
    asm("fma.rn.f32x2 %0, %1, %2, %0;" : "+l"(acc) : "l"(a), "l"(b));
}

// ---------- cp.async helpers ----------
__device__ __forceinline__ void cp16(void *smem, const void *gmem) {
    unsigned saddr = (unsigned)__cvta_generic_to_shared(smem);
    asm volatile("cp.async.cg.shared.global [%0], [%1], 16;" :: "r"(saddr), "l"(gmem));
}
__device__ __forceinline__ void cp_commit() {
    asm volatile("cp.async.commit_group;" ::: "memory");
}
template <int N>
__device__ __forceinline__ void cp_wait() {
    asm volatile("cp.async.wait_group %0;" :: "n"(N) : "memory");
}

// ============================================================
// Kernel 1: partial GEMM  partial[cta] += F[:, krange] @ W1[krange, :]
// F generated on the fly: F[b,k] = a_h[b,i]*v_h[b,j]*t_h[b,kq],
// k = (i*129 + j)*129 + kq,  x_h[b,0] = 1, x_h[b,1+r] = x[b,r]
// ============================================================
__global__ void __launch_bounds__(NTHR, 2)
k_main(const float* __restrict__ v, const float* __restrict__ a,
       const float* __restrict__ t, const float* __restrict__ W1)
{
    __shared__ float sW[2][TK][N1];   // 16 KB  (double-buffered W1 tile)
    __shared__ float sF[TK][Bq];      //  8 KB  (fusion tile)

    const int tid = threadIdx.x;
    const int cta = blockIdx.x;

    const int kpc = (FUSE + NCTA - 1) / NCTA;          // 7062
    const int k0  = cta * kpc;
    const int k1  = min(FUSE, k0 + kpc);
    const int ntiles = (k1 - k0 + TK - 1) / TK;        // >= 1 for all ctas

    // thread tile: 4 outputs x 4 batches
    const int obk = tid >> 4;          // 0..15
    const int bbk = tid & 15;          // 0..15
    const int o0  = obk * 4;
    const int b0  = bbk * 4;

    unsigned long long acc[8];
    #pragma unroll
    for (int i = 0; i < 8; i++) acc[i] = 0ull;   // (0.f,0.f)

    // --- W1 tile loader (clamped; clamped/overhang rows are killed by f=0) ---
    auto issue = [&](int tileIdx, int buf) {
        const int kb = k0 + tileIdx * TK;
        #pragma unroll
        for (int q = tid; q < TK * 16; q += NTHR) {  // 512 16B chunks
            int kk  = q >> 4;
            int seg = q & 15;
            int kg  = kb + kk;
            if (kg >= FUSE) kg = FUSE - 1;           // clamp (stays in-bounds)
            cp16(&sW[buf][kk][seg * 4], W1 + (long long)kg * N1 + seg * 4);
        }
        cp_commit();
    };

    // --- fusion tile generator ---
    // NOTE: guard is the PER-CTA bound k1, not FUSE. kpc is not a multiple of
    // TK, so the last tile of every CTA overhangs its range by up to TK-1
    // k-columns; those columns belong to the next CTA and must contribute 0
    // here (guarding only against FUSE double-counted them => rel_err 5.4e-2).
    auto genF = [&](int tileIdx) {
        const int kb = k0 + tileIdx * TK;
        #pragma unroll
        for (int p = 0; p < (TK * Bq) / NTHR; p++) { // 8 passes
            int idx = p * NTHR + tid;
            int kk  = idx >> 6;
            int b   = idx & 63;
            int kg  = kb + kk;
            float f = 0.f;
            if (kg < k1) {
                int i   = kg / (H1c * H1c);
                int rem = kg - i * (H1c * H1c);
                int j   = rem / H1c;
                int kq  = rem - j * H1c;
                float av = (i  == 0) ? 1.f : __ldg(&a[b * Hc + (i - 1)]);
                float vv = (j  == 0) ? 1.f : __ldg(&v[b * Hc + (j - 1)]);
                float tv = (kq == 0) ? 1.f : __ldg(&t[b * Hc + (kq - 1)]);
                f = av * vv * tv;
            }
            sF[kk][b] = f;
        }
    };

    issue(0, 0);

    for (int tl = 0; tl < ntiles; tl++) {
        const int buf = tl & 1;
        if (tl + 1 < ntiles) { issue(tl + 1, buf ^ 1); cp_wait<1>(); }
        else                 { cp_wait<0>(); }
        __syncthreads();          // sW[buf] ready for everyone
        genF(tl);
        __syncthreads();          // sF ready

        #pragma unroll
        for (int kk = 0; kk < TK; kk++) {
            const ulonglong2 w = *reinterpret_cast<const ulonglong2*>(&sW[buf][kk][o0]);
            const float4     f = *reinterpret_cast<const float4*>(&sF[kk][b0]);
            unsigned long long f0 = pack2(f.x, f.x);
            unsigned long long f1 = pack2(f.y, f.y);
            unsigned long long f2 = pack2(f.z, f.z);
            unsigned long long f3 = pack2(f.w, f.w);
            ffma2(acc[0], w.x, f0); ffma2(acc[1], w.y, f0);
            ffma2(acc[2], w.x, f1); ffma2(acc[3], w.y, f1);
            ffma2(acc[4], w.x, f2); ffma2(acc[5], w.y, f2);
            ffma2(acc[6], w.x, f3); ffma2(acc[7], w.y, f3);
        }
        __syncthreads();          // done reading sW[buf] / sF before overwrite
    }

    // write partial tile
    float *out = &g_partial[cta * (Bq * N1)];
    #pragma unroll
    for (int bi = 0; bi < 4; bi++) {
        float x0, x1, x2, x3;
        unpack2(acc[2 * bi + 0], x0, x1);
        unpack2(acc[2 * bi + 1], x2, x3);
        float *row = out + (b0 + bi) * N1 + o0;
        row[0] = x0; row[1] = x1; row[2] = x2; row[3] = x3;
    }
}

// ============================================================
// Kernel 2: reduce partials, +b1, relu -> g_Y1
// ============================================================
__global__ void k_reduce(const float* __restrict__ b1)
{
    int tix = blockIdx.x * blockDim.x + threadIdx.x;   // 0..4095
    float s = 0.f;
    #pragma unroll 4
    for (int c = 0; c < NCTA; c++)
        s += g_partial[c * (Bq * N1) + tix];
    s += b1[tix & (N1 - 1)];
    g_Y1[tix] = fmaxf(s, 0.f);
}

// ============================================================
// Kernel 3: tail MLP  y2 = relu(Y1 @ W2 + b2); out = y2 @ W3 + b3
// ============================================================
__global__ void k_tail(const float* __restrict__ W2, const float* __restrict__ b2,
                       const float* __restrict__ W3, const float* __restrict__ b3,
                       float* __restrict__ out)
{
    __shared__ float sW2[N1 * N2];
    __shared__ float sW3[N2];
    int tid = threadIdx.x;
    for (int i = tid; i < N1 * N2; i += 64) sW2[i] = W2[i];
    if (tid < N2) sW3[tid] = W3[tid];
    __syncthreads();

    if (tid < Bq) {
        float y1[N1];
        #pragma unroll
        for (int o = 0; o < N1; o++) y1[o] = g_Y1[tid * N1 + o];
        float r = b3[0];
        #pragma unroll 4
        for (int j = 0; j < N2; j++) {
            float s = b2[j];
            #pragma unroll
            for (int o = 0; o < N1; o++) s += y1[o] * sW2[o * N2 + j];
            r += fmaxf(s, 0.f) * sW3[j];
        }
        out[tid] = r;
    }
}

// ============================================================
// Launch
// inputs (metadata order): v, a, t, W1, b1, W2, b2, W3, b3 ; out: float[64]
// ============================================================
extern "C" void kernel_launch(void* const* d_in, const int* in_sizes, int n_in,
                              void* d_out, int out_size)
{
    const float *v  = (const float*)d_in[0];
    const float *a  = (const float*)d_in[1];
    const float *t  = (const float*)d_in[2];
    const float *W1 = (const float*)d_in[3];
    const float *b1 = (const float*)d_in[4];
    const float *W2 = (const float*)d_in[5];
    const float *b2 = (const float*)d_in[6];
    const float *W3 = (const float*)d_in[7];
    const float *b3 = (const float*)d_in[8];
    float *out = (float*)d_out;

    k_main<<<NCTA, NTHR>>>(v, a, t, W1);
    k_reduce<<<(Bq * N1) / 256, 256>>>(b1);
    k_tail<<<1, 64>>>(W2, b2, W3, b3, out);
}

// round 6
// speedup vs baseline: 3.2041x; 3.2041x over previous
#include <cuda_runtime.h>
#include <cstdint>

// Problem constants
#define Hc    128
#define H1c   129
#define FUSE  (H1c*H1c*H1c)     // 2,146,689
#define NROW  (H1c*H1c)         // 16641 (i,j) rows, each 129 kq long
#define Bq    64                // batch
#define N1    64                // H/2
#define N2    32                // H/4
#define TK    32                // k-tile
#define NCTA  304
#define NTHR  256
#define RPC   55                // kq-rows per CTA (55*304 = 16720 >= 16641)
#define KPC   (RPC*H1c)         // 7095 k per CTA

// Scratch (no cudaMalloc allowed)
__device__ float g_partial[NCTA * Bq * N1];   // ~5 MB
__device__ float g_Y1[Bq * N1];
__device__ float g_pm[NROW * Bq];             // pm[r][b] = a_h[b,i]*v_h[b,j]  (4.26 MB)
__device__ float g_tT[H1c * Bq];              // tT[kq][b] = t_h[b,kq]         (33 KB)

// ---------- packed f32x2 helpers ----------
__device__ __forceinline__ unsigned long long pack2(float lo, float hi) {
    unsigned long long r;
    asm("mov.b64 %0, {%1, %2};" : "=l"(r)
        : "r"(__float_as_uint(lo)), "r"(__float_as_uint(hi)));
    return r;
}
__device__ __forceinline__ void unpack2(unsigned long long x, float &lo, float &hi) {
    unsigned a, b;
    asm("mov.b64 {%0, %1}, %2;" : "=r"(a), "=r"(b) : "l"(x));
    lo = __uint_as_float(a); hi = __uint_as_float(b);
}
__device__ __forceinline__ void ffma2(unsigned long long &acc,
                                      unsigned long long a, unsigned long long b) {
    asm("fma.rn.f32x2 %0, %1, %2, %0;" : "+l"(acc) : "l"(a), "l"(b));
}

// ---------- cp.async helpers ----------
__device__ __forceinline__ void cp16(void *smem, const void *gmem) {
    unsigned saddr = (unsigned)__cvta_generic_to_shared(smem);
    asm volatile("cp.async.cg.shared.global [%0], [%1], 16;" :: "r"(saddr), "l"(gmem));
}
__device__ __forceinline__ void cp_commit() {
    asm volatile("cp.async.commit_group;" ::: "memory");
}
template <int N>
__device__ __forceinline__ void cp_wait() {
    asm volatile("cp.async.wait_group %0;" :: "n"(N) : "memory");
}

// ============================================================
// Kernel 0: prep — factor the fusion tensor.
//   g_pm[r*64+b] = a_h[b, r/129] * v_h[b, r%129]
//   g_tT[kq*64+b] = t_h[b, kq]
// Coalesced in b (consecutive lanes -> consecutive b).
// ============================================================
__global__ void k_prep(const float* __restrict__ v, const float* __restrict__ a,
                       const float* __restrict__ t)
{
    int idx = blockIdx.x * blockDim.x + threadIdx.x;
    int b = idx & (Bq - 1);
    int r = idx >> 6;
    if (r < NROW) {
        int i = r / H1c;
        int j = r - i * H1c;
        float av = (i == 0) ? 1.f : __ldg(&a[b * Hc + (i - 1)]);
        float vv = (j == 0) ? 1.f : __ldg(&v[b * Hc + (j - 1)]);
        g_pm[idx] = av * vv;
    } else if (r < NROW + H1c) {
        int kq = r - NROW;
        g_tT[kq * Bq + b] = (kq == 0) ? 1.f : __ldg(&t[b * Hc + (kq - 1)]);
    }
}

// ============================================================
// Kernel 1: partial GEMM  partial[cta] = F[:, krange] @ W1[krange, :]
// CTA cta owns kq-rows [cta*RPC, cta*RPC+nrows), k-range [k0, k0+nk).
// F generated on the fly from g_pm / g_tT (both coalesced L1-hot).
// ============================================================
__global__ void __launch_bounds__(NTHR, 2)
k_main(const float* __restrict__ W1)
{
    __shared__ float sW[2][TK][N1];   // 16 KB (double-buffered W1 tile)
    __shared__ float sF[TK][Bq];      //  8 KB (fusion tile)

    const int tid = threadIdx.x;
    const int cta = blockIdx.x;

    const int r0     = cta * RPC;
    const int nrows  = (r0 < NROW) ? min(RPC, NROW - r0) : 0;
    const int nk     = nrows * H1c;                  // k's this CTA owns
    const int ntiles = (nk + TK - 1) / TK;
    const long long k0 = (long long)r0 * H1c;

    // thread tile: 4 outputs x 4 batches
    const int o0 = (tid >> 4) * 4;
    const int b0 = (tid & 15) * 4;

    unsigned long long acc[8];
    #pragma unroll
    for (int i = 0; i < 8; i++) acc[i] = 0ull;

    if (ntiles > 0) {
        // --- W1 tile loader (clamped; overhang rows killed by f=0) ---
        auto issue = [&](int tileIdx, int buf) {
            const long long kb = k0 + (long long)tileIdx * TK;
            #pragma unroll
            for (int q = tid; q < TK * 16; q += NTHR) {  // 512 16B chunks
                int kk  = q >> 4;
                int seg = q & 15;
                long long kg = kb + kk;
                if (kg >= FUSE) kg = FUSE - 1;           // clamp (stays in-bounds)
                cp16(&sW[buf][kk][seg * 4], W1 + kg * N1 + seg * 4);
            }
            cp_commit();
        };

        // --- fusion tile generator: f = pm[row] * tT[kq], coalesced in b ---
        auto genF = [&](int tileIdx) {
            const int kbl = tileIdx * TK;                // local k base
            #pragma unroll
            for (int p = 0; p < (TK * Bq) / NTHR; p++) { // 8 passes
                int idx = p * NTHR + tid;
                int kk  = idx >> 6;
                int b   = idx & (Bq - 1);
                int kl  = kbl + kk;
                float f = 0.f;
                if (kl < nk) {                           // per-CTA bound!
                    int row = kl / H1c;                  // local row
                    int kq  = kl - row * H1c;
                    f = __ldg(&g_pm[(r0 + row) * Bq + b]) * __ldg(&g_tT[kq * Bq + b]);
                }
                sF[kk][b] = f;
            }
        };

        issue(0, 0);

        for (int tl = 0; tl < ntiles; tl++) {
            const int buf = tl & 1;
            if (tl + 1 < ntiles) { issue(tl + 1, buf ^ 1); cp_wait<1>(); }
            else                 { cp_wait<0>(); }
            __syncthreads();          // sW[buf] ready for everyone
            genF(tl);
            __syncthreads();          // sF ready

            #pragma unroll
            for (int kk = 0; kk < TK; kk++) {
                const ulonglong2 w = *reinterpret_cast<const ulonglong2*>(&sW[buf][kk][o0]);
                const float4     f = *reinterpret_cast<const float4*>(&sF[kk][b0]);
                unsigned long long f0 = pack2(f.x, f.x);
                unsigned long long f1 = pack2(f.y, f.y);
                unsigned long long f2 = pack2(f.z, f.z);
                unsigned long long f3 = pack2(f.w, f.w);
                ffma2(acc[0], w.x, f0); ffma2(acc[1], w.y, f0);
                ffma2(acc[2], w.x, f1); ffma2(acc[3], w.y, f1);
                ffma2(acc[4], w.x, f2); ffma2(acc[5], w.y, f2);
                ffma2(acc[6], w.x, f3); ffma2(acc[7], w.y, f3);
            }
            __syncthreads();          // done reading sW[buf]/sF before overwrite
        }
    }

    // write partial tile (zeros for idle CTAs)
    float *out = &g_partial[cta * (Bq * N1)];
    #pragma unroll
    for (int bi = 0; bi < 4; bi++) {
        float x0, x1, x2, x3;
        unpack2(acc[2 * bi + 0], x0, x1);
        unpack2(acc[2 * bi + 1], x2, x3);
        float *row = out + (b0 + bi) * N1 + o0;
        row[0] = x0; row[1] = x1; row[2] = x2; row[3] = x3;
    }
}

// ============================================================
// Kernel 2: reduce partials, +b1, relu -> g_Y1
// ============================================================
__global__ void k_reduce(const float* __restrict__ b1)
{
    int tix = blockIdx.x * blockDim.x + threadIdx.x;   // 0..4095
    float s = 0.f;
    #pragma unroll 4
    for (int c = 0; c < NCTA; c++)
        s += g_partial[c * (Bq * N1) + tix];
    s += b1[tix & (N1 - 1)];
    g_Y1[tix] = fmaxf(s, 0.f);
}

// ============================================================
// Kernel 3: tail MLP  y2 = relu(Y1 @ W2 + b2); out = y2 @ W3 + b3
// ============================================================
__global__ void k_tail(const float* __restrict__ W2, const float* __restrict__ b2,
                       const float* __restrict__ W3, const float* __restrict__ b3,
                       float* __restrict__ out)
{
    __shared__ float sW2[N1 * N2];
    __shared__ float sW3[N2];
    int tid = threadIdx.x;
    for (int i = tid; i < N1 * N2; i += 64) sW2[i] = W2[i];
    if (tid < N2) sW3[tid] = W3[tid];
    __syncthreads();

    if (tid < Bq) {
        float y1[N1];
        #pragma unroll
        for (int o = 0; o < N1; o++) y1[o] = g_Y1[tid * N1 + o];
        float r = b3[0];
        #pragma unroll 4
        for (int j = 0; j < N2; j++) {
            float s = b2[j];
            #pragma unroll
            for (int o = 0; o < N1; o++) s += y1[o] * sW2[o * N2 + j];
            r += fmaxf(s, 0.f) * sW3[j];
        }
        out[tid] = r;
    }
}

// ============================================================
// Launch
// inputs (metadata order): v, a, t, W1, b1, W2, b2, W3, b3 ; out: float[64]
// ============================================================
extern "C" void kernel_launch(void* const* d_in, const int* in_sizes, int n_in,
                              void* d_out, int out_size)
{
    const float *v  = (const float*)d_in[0];
    const float *a  = (const float*)d_in[1];
    const float *t  = (const float*)d_in[2];
    const float *W1 = (const float*)d_in[3];
    const float *b1 = (const float*)d_in[4];
    const float *W2 = (const float*)d_in[5];
    const float *b2 = (const float*)d_in[6];
    const float *W3 = (const float*)d_in[7];
    const float *b3 = (const float*)d_in[8];
    float *out = (float*)d_out;

    const int prep_elems = (NROW + H1c) * Bq;
    k_prep<<<(prep_elems + NTHR - 1) / NTHR, NTHR>>>(v, a, t);
    k_main<<<NCTA, NTHR>>>(W1);
    k_reduce<<<(Bq * N1) / 256, 256>>>(b1);
    k_tail<<<1, 64>>>(W2, b2, W3, b3, out);
}

// round 8
// speedup vs baseline: 6.8988x; 2.1531x over previous
#include <cuda_runtime.h>
#include <cstdint>

// ---------------- problem constants ----------------
#define Hc    128
#define H1c   129
#define FUSE  (H1c*H1c*H1c)     // 2,146,689
#define NROW  (H1c*H1c)         // 16641
#define Bq    64
#define N1    64
#define N2    32
#define TK    32                // k per tile (4 mma k-steps of 8)
#define NCTA  304
#define NTHR  256
#define RPC   55                // kq-rows per CTA (55*304 >= 16641)

#define SA_STRIDE 36            // floats per A row (conflict-free frag loads)
#define SB_STRIDE 72            // floats per B k-row (conflict-free frag loads)

__device__ float g_partial[NCTA * Bq * N1];   // ~5 MB
__device__ float g_Y1[Bq * N1];
__device__ float g_pm[NROW * Bq];             // pm[r][b] = a_h[b,i]*v_h[b,j]
__device__ float g_tT2[Bq * H1c];             // tT2[b][kq] = t_h[b,kq]

// ---------------- helpers ----------------
__device__ __forceinline__ uint32_t smem_u32(const void* p) {
    uint32_t a;
    asm("{ .reg .u64 t; cvta.to.shared.u64 t, %1; cvt.u32.u64 %0, t; }" : "=r"(a) : "l"(p));
    return a;
}
__device__ __forceinline__ void cp16(uint32_t saddr, const void* g) {
    asm volatile("cp.async.cg.shared.global [%0], [%1], 16;" :: "r"(saddr), "l"(g));
}
__device__ __forceinline__ void cp_commit() { asm volatile("cp.async.commit_group;" ::: "memory"); }
template <int N> __device__ __forceinline__ void cp_wait() {
    asm volatile("cp.async.wait_group %0;" :: "n"(N) : "memory");
}
__device__ __forceinline__ uint32_t to_tf32(float f) {
    uint32_t u;
    asm("cvt.rna.tf32.f32 %0, %1;" : "=r"(u) : "f"(f));
    return u;
}
// D(16x8,f32) += A(16x8,tf32) * B(8x8,tf32)   row.col
__device__ __forceinline__ void mma_tf32(float* d, const uint32_t* a,
                                         uint32_t b0, uint32_t b1) {
    asm volatile(
        "mma.sync.aligned.m16n8k8.row.col.f32.tf32.tf32.f32 "
        "{%0,%1,%2,%3}, {%4,%5,%6,%7}, {%8,%9}, {%0,%1,%2,%3};"
        : "+f"(d[0]), "+f"(d[1]), "+f"(d[2]), "+f"(d[3])
        : "r"(a[0]), "r"(a[1]), "r"(a[2]), "r"(a[3]), "r"(b0), "r"(b1));
}

// ============================================================
// Kernel 0: prep
//   g_pm[r*64+b]   = a_h[b, r/129] * v_h[b, r%129]   (coalesced in b)
//   g_tT2[b*129+kq] = t_h[b, kq]                      (t transposed)
// ============================================================
__global__ void k_prep(const float* __restrict__ v, const float* __restrict__ a,
                       const float* __restrict__ t)
{
    int idx = blockIdx.x * blockDim.x + threadIdx.x;
    if (idx < NROW * Bq) {
        int b = idx & (Bq - 1);
        int r = idx >> 6;
        int i = r / H1c;
        int j = r - i * H1c;
        float av = (i == 0) ? 1.f : __ldg(&a[b * Hc + (i - 1)]);
        float vv = (j == 0) ? 1.f : __ldg(&v[b * Hc + (j - 1)]);
        g_pm[idx] = av * vv;
    } else if (idx < NROW * Bq + Bq * H1c) {
        int j  = idx - NROW * Bq;
        int b  = j / H1c;
        int kq = j - b * H1c;
        g_tT2[j] = (kq == 0) ? 1.f : __ldg(&t[b * Hc + (kq - 1)]);
    }
}

// ============================================================
// Kernel 1: tf32 mma.sync partial GEMM
//   D[64 b, 64 n] per CTA over its k-range; 4 compute warps, m32n32 tiles.
//   sB[buf] = W1 tile [32 k][64 n] (stride 72), filled directly by cp.async
//   sA[buf] = F tile  [64 b][32 k] (stride 36), tf32-rounded by genF
// ============================================================
__global__ void __launch_bounds__(NTHR, 2)
k_main_mma(const float* __restrict__ W1)
{
    __shared__ float sA[2][Bq * SA_STRIDE];   // 2 x 9216 B
    __shared__ float sB[2][TK * SB_STRIDE];   // 2 x 9216 B

    const int tid  = threadIdx.x;
    const int wid  = tid >> 5;
    const int lane = tid & 31;
    const int cta  = blockIdx.x;

    const int r0     = cta * RPC;
    const int nrows  = (r0 < NROW) ? min(RPC, NROW - r0) : 0;
    const int nk     = nrows * H1c;
    const int ntiles = (nk + TK - 1) / TK;
    const long long k0 = (long long)r0 * H1c;

    if (ntiles == 0) {            // idle CTA: zero partial, uniform exit
        float* out = &g_partial[cta * (Bq * N1)];
        for (int i = tid; i < Bq * N1; i += NTHR) out[i] = 0.f;
        return;
    }

    const uint32_t sBu = smem_u32(sB);

    // --- W1 tile -> sB[buf] via cp.async (stride-72 rows, 16B chunks) ---
    auto issue = [&](int tl, int buf) {
        const long long kb = k0 + (long long)tl * TK;
        #pragma unroll
        for (int q = tid; q < TK * 16; q += NTHR) {   // 512 x 16B
            int kk  = q >> 4;
            int seg = q & 15;
            long long kg = kb + kk;
            if (kg >= FUSE) kg = FUSE - 1;            // clamp; f=0 kills overhang
            cp16(sBu + buf * (TK * SB_STRIDE * 4) + kk * (SB_STRIDE * 4) + seg * 16,
                 W1 + kg * N1 + seg * 4);
        }
        cp_commit();
    };

    // --- F tile -> sA[buf]; lanes walk k (conflict-free STS, coalesced LDG) ---
    auto genF = [&](int tl, int buf) {
        const int kbl = tl * TK;
        #pragma unroll
        for (int p = 0; p < 8; p++) {
            int b  = p * 8 + wid;                      // one b per warp per pass
            int kl = kbl + lane;
            float f = 0.f;
            if (kl < nk) {
                int row = kl / H1c;
                int kq  = kl - row * H1c;
                f = __ldg(&g_pm[(r0 + row) * Bq + b]) * __ldg(&g_tT2[b * H1c + kq]);
            }
            sA[buf][b * SA_STRIDE + lane] = __uint_as_float(to_tf32(f));
        }
    };

    // compute-warp geometry (warps 0..3, m32n32 each)
    const int wm = wid & 1;           // m32 block
    const int wn = (wid >> 1) & 1;    // n32 block
    const int g  = lane >> 2;         // groupID 0..7
    const int tk = lane & 3;          // threadID-in-group 0..3

    float acc[2][4][4];               // [mi(2 m16)][nj(4 n8)][4]
    #pragma unroll
    for (int mi = 0; mi < 2; mi++)
        #pragma unroll
        for (int nj = 0; nj < 4; nj++)
            #pragma unroll
            for (int q = 0; q < 4; q++) acc[mi][nj][q] = 0.f;

    issue(0, 0);

    for (int tl = 0; tl < ntiles; tl++) {
        const int buf = tl & 1;
        if (tl + 1 < ntiles) { issue(tl + 1, buf ^ 1); cp_wait<1>(); }
        else                 { cp_wait<0>(); }
        __syncthreads();              // sB[buf] visible to all
        genF(tl, buf);
        __syncthreads();              // sA[buf] ready

        if (wid < 4) {
            #pragma unroll
            for (int ks = 0; ks < 4; ks++) {
                // A fragments for both m16 sub-tiles
                uint32_t a[2][4];
                const int c = ks * 8 + tk;
                #pragma unroll
                for (int mi = 0; mi < 2; mi++) {
                    const int r = wm * 32 + mi * 16 + g;
                    a[mi][0] = __float_as_uint(sA[buf][r        * SA_STRIDE + c]);
                    a[mi][1] = __float_as_uint(sA[buf][(r + 8)  * SA_STRIDE + c]);
                    a[mi][2] = __float_as_uint(sA[buf][r        * SA_STRIDE + c + 4]);
                    a[mi][3] = __float_as_uint(sA[buf][(r + 8)  * SA_STRIDE + c + 4]);
                }
                #pragma unroll
                for (int nj = 0; nj < 4; nj++) {
                    const int n = wn * 32 + nj * 8 + g;
                    uint32_t b0 = to_tf32(sB[buf][(ks * 8 + tk)     * SB_STRIDE + n]);
                    uint32_t b1 = to_tf32(sB[buf][(ks * 8 + 4 + tk) * SB_STRIDE + n]);
                    mma_tf32(acc[0][nj], a[0], b0, b1);
                    mma_tf32(acc[1][nj], a[1], b0, b1);
                }
            }
        }
        __syncthreads();              // done reading sA/sB[buf] before overwrite
    }

    // --- write partial tile: D element (row, col): rows g,g+8; cols 2tk,2tk+1 ---
    if (wid < 4) {
        float* base = &g_partial[cta * (Bq * N1)];
        #pragma unroll
        for (int mi = 0; mi < 2; mi++) {
            const int r = wm * 32 + mi * 16 + g;
            #pragma unroll
            for (int nj = 0; nj < 4; nj++) {
                const int n = wn * 32 + nj * 8 + 2 * tk;
                *reinterpret_cast<float2*>(base + r * N1 + n) =
                    make_float2(acc[mi][nj][0], acc[mi][nj][1]);
                *reinterpret_cast<float2*>(base + (r + 8) * N1 + n) =
                    make_float2(acc[mi][nj][2], acc[mi][nj][3]);
            }
        }
    }
}

// ============================================================
// Kernel 2: reduce partials, +b1, relu -> g_Y1
// ============================================================
__global__ void k_reduce(const float* __restrict__ b1)
{
    int tix = blockIdx.x * blockDim.x + threadIdx.x;   // 0..4095
    float s = 0.f;
    #pragma unroll 4
    for (int c = 0; c < NCTA; c++)
        s += g_partial[c * (Bq * N1) + tix];
    s += b1[tix & (N1 - 1)];
    g_Y1[tix] = fmaxf(s, 0.f);
}

// ============================================================
// Kernel 3: tail MLP
// ============================================================
__global__ void k_tail(const float* __restrict__ W2, const float* __restrict__ b2,
                       const float* __restrict__ W3, const float* __restrict__ b3,
                       float* __restrict__ out)
{
    __shared__ float sW2[N1 * N2];
    __shared__ float sW3[N2];
    int tid = threadIdx.x;
    for (int i = tid; i < N1 * N2; i += 64) sW2[i] = W2[i];
    if (tid < N2) sW3[tid] = W3[tid];
    __syncthreads();

    if (tid < Bq) {
        float y1[N1];
        #pragma unroll
        for (int o = 0; o < N1; o++) y1[o] = g_Y1[tid * N1 + o];
        float r = b3[0];
        #pragma unroll 4
        for (int j = 0; j < N2; j++) {
            float s = b2[j];
            #pragma unroll
            for (int o = 0; o < N1; o++) s += y1[o] * sW2[o * N2 + j];
            r += fmaxf(s, 0.f) * sW3[j];
        }
        out[tid] = r;
    }
}

// ============================================================
// Launch: v, a, t, W1, b1, W2, b2, W3, b3 ; out float[64]
// ============================================================
extern "C" void kernel_launch(void* const* d_in, const int* in_sizes, int n_in,
                              void* d_out, int out_size)
{
    const float *v  = (const float*)d_in[0];
    const float *a  = (const float*)d_in[1];
    const float *t  = (const float*)d_in[2];
    const float *W1 = (const float*)d_in[3];
    const float *b1 = (const float*)d_in[4];
    const float *W2 = (const float*)d_in[5];
    const float *b2 = (const float*)d_in[6];
    const float *W3 = (const float*)d_in[7];
    const float *b3 = (const float*)d_in[8];
    float *out = (float*)d_out;

    const int prep_elems = NROW * Bq + Bq * H1c;
    k_prep<<<(prep_elems + NTHR - 1) / NTHR, NTHR>>>(v, a, t);
    k_main_mma<<<NCTA, NTHR>>>(W1);
    k_reduce<<<(Bq * N1) / 256, 256>>>(b1);
    k_tail<<<1, 64>>>(W2, b2, W3, b3, out);
}